// round 3
// baseline (speedup 1.0000x reference)
#include <cuda_runtime.h>
#include <cstddef>

typedef unsigned long long ull;

// ---------------- scratch (static device globals; no allocation) ----------------
__device__ float g_h64[4096 * 64];     // LSTM1 final hidden
__device__ float g_h256[4096 * 256];   // LSTM2 hidden

// ---------------- packed f32x2 helpers ----------------
__device__ __forceinline__ ull pk(float lo, float hi) {
    ull r;
    asm("mov.b64 %0, {%1, %2};" : "=l"(r) : "f"(lo), "f"(hi));
    return r;
}
__device__ __forceinline__ void fma2(ull& d, ull a, ull b) {
    asm("fma.rn.f32x2 %0, %1, %2, %0;" : "+l"(d) : "l"(a), "l"(b));
}
__device__ __forceinline__ float2 upk(ull v) {
    float2 r;
    asm("mov.b64 {%0, %1}, %2;" : "=f"(r.x), "=f"(r.y) : "l"(v));
    return r;
}

// accurate-enough activations (expf ~2ulp; robust at +-inf limits)
__device__ __forceinline__ float sigf(float x) {
    return __fdividef(1.0f, 1.0f + __expf(-x));
}
__device__ __forceinline__ float tanh_(float x) {
    return __fdividef(2.0f, 1.0f + __expf(-2.0f * x)) - 1.0f;
}

// ---------------- shared layout for LSTM1 (floats) ----------------
// Wsh  [84][256]   : 21504
// act  [84][32]    :  2688  (rows 0..19 = emb, rows 20..83 = h)
// gbuf [256][33]   :  8448  (padded to kill bank conflicts)
// cst  [64][32]    :  2048
// bsh  [256]       :   256
// eW   [64]        :    64  (W_embed, 40 used)
#define S1_WSH   0
#define S1_ACT   21504
#define S1_GBUF  (21504 + 2688)
#define S1_CST   (S1_GBUF + 8448)
#define S1_BSH   (S1_CST + 2048)
#define S1_EW    (S1_BSH + 256)
#define S1_FLOATS (S1_EW + 64)          // 35008 floats = 140032 bytes

__global__ void __launch_bounds__(256, 1)
lstm1_kernel(const float* __restrict__ x,
             const float* __restrict__ W_embed,
             const float* __restrict__ Wih1,
             const float* __restrict__ Whh1,
             const float* __restrict__ b1)
{
    extern __shared__ float sm[];
    float* Wsh  = sm + S1_WSH;
    float* act  = sm + S1_ACT;
    float* gbuf = sm + S1_GBUF;
    float* cst  = sm + S1_CST;
    float* bsh  = sm + S1_BSH;
    float* eW   = sm + S1_EW;

    const int tid = threadIdx.x;
    const int bt  = blockIdx.x;          // batch tile (32 elems)

    // load combined weight [k][gate]: k<20 -> Wih1[g][k], else Whh1[g][k-20]
    for (int idx = tid; idx < 84 * 256; idx += 256) {
        int k = idx >> 8, g = idx & 255;
        Wsh[idx] = (k < 20) ? __ldg(&Wih1[g * 20 + k])
                            : __ldg(&Whh1[g * 64 + (k - 20)]);
    }
    bsh[tid] = b1[tid];
    if (tid < 40) eW[tid] = W_embed[tid];
    // zero h rows of act and cell state
    for (int idx = tid; idx < 64 * 32; idx += 256) {
        act[20 * 32 + idx] = 0.0f;
        cst[idx] = 0.0f;
    }
    __syncthreads();

    // token prefetch + embedding for t=0
    const float2* xrow = reinterpret_cast<const float2*>(x) +
                         (size_t)(bt * 32 + (tid & 31)) * 512;
    float2 tok_next = make_float2(0.0f, 0.0f);
    if (tid < 32) {
        float2 t0 = xrow[0];
        #pragma unroll
        for (int e = 0; e < 20; e++) {
            float v = fmaf(t0.x, eW[2 * e], t0.y * eW[2 * e + 1]);
            act[e * 32 + tid] = fmaxf(v, 0.0f);
        }
        tok_next = xrow[1];
    }
    __syncthreads();

    // matmul thread mapping: warp -> 8 batches x 128 gates, lane -> 2 gate-pairs
    const int w = tid >> 5, l = tid & 31;
    const int bg = w >> 1;               // batch octet 0..3
    const int half = w & 1;              // gate half 0..1
    const float* wbase = Wsh + half * 128 + 2 * l;
    const float* abase = act + bg * 8;
    const int g0 = half * 128 + 2 * l;   // first gate of pair 0 (pair1 at g0+64)
    const ull bp0 = pk(bsh[g0],      bsh[g0 + 1]);
    const ull bp1 = pk(bsh[g0 + 64], bsh[g0 + 65]);
    const int pb = tid & 31;             // pointwise batch
    const int pj0 = (tid >> 5) * 8;      // pointwise j base

    for (int t = 0; t < 512; t++) {
        // ---- phase A: gates = act^T W + b (packed f32x2) ----
        ull acc0[8], acc1[8];
        #pragma unroll
        for (int q = 0; q < 8; q++) { acc0[q] = bp0; acc1[q] = bp1; }

        #pragma unroll 4
        for (int k = 0; k < 84; k++) {
            float4 aA = *reinterpret_cast<const float4*>(abase + k * 32);
            float4 aB = *reinterpret_cast<const float4*>(abase + k * 32 + 4);
            ull a0 = pk(aA.x, aA.x), a1 = pk(aA.y, aA.y);
            ull a2 = pk(aA.z, aA.z), a3 = pk(aA.w, aA.w);
            ull a4 = pk(aB.x, aB.x), a5 = pk(aB.y, aB.y);
            ull a6 = pk(aB.z, aB.z), a7 = pk(aB.w, aB.w);
            float2 w0 = *reinterpret_cast<const float2*>(wbase + k * 256);
            float2 w1 = *reinterpret_cast<const float2*>(wbase + k * 256 + 64);
            ull wp0 = pk(w0.x, w0.y);
            ull wp1 = pk(w1.x, w1.y);
            fma2(acc0[0], wp0, a0); fma2(acc0[1], wp0, a1);
            fma2(acc0[2], wp0, a2); fma2(acc0[3], wp0, a3);
            fma2(acc0[4], wp0, a4); fma2(acc0[5], wp0, a5);
            fma2(acc0[6], wp0, a6); fma2(acc0[7], wp0, a7);
            fma2(acc1[0], wp1, a0); fma2(acc1[1], wp1, a1);
            fma2(acc1[2], wp1, a2); fma2(acc1[3], wp1, a3);
            fma2(acc1[4], wp1, a4); fma2(acc1[5], wp1, a5);
            fma2(acc1[6], wp1, a6); fma2(acc1[7], wp1, a7);
        }

        // ---- phase B: spill gates to shared ----
        #pragma unroll
        for (int q = 0; q < 8; q++) {
            float2 v0 = upk(acc0[q]);
            float2 v1 = upk(acc1[q]);
            int bb = bg * 8 + q;
            gbuf[(g0)      * 33 + bb] = v0.x;
            gbuf[(g0 + 1)  * 33 + bb] = v0.y;
            gbuf[(g0 + 64) * 33 + bb] = v1.x;
            gbuf[(g0 + 65) * 33 + bb] = v1.y;
        }
        __syncthreads();

        // ---- phase C: pointwise LSTM cell + next-step embedding ----
        #pragma unroll
        for (int mm = 0; mm < 8; mm++) {
            int j = pj0 + mm;
            float gi = gbuf[j * 33 + pb];
            float gf = gbuf[(64 + j) * 33 + pb];
            float gg = gbuf[(128 + j) * 33 + pb];
            float go = gbuf[(192 + j) * 33 + pb];
            float c  = cst[j * 32 + pb];
            float cn = fmaf(sigf(gf), c, sigf(gi) * tanh_(gg));
            float h  = sigf(go) * tanh_(cn);
            cst[j * 32 + pb] = cn;
            act[(20 + j) * 32 + pb] = h;
        }
        if (tid < 32 && t < 511) {
            #pragma unroll
            for (int e = 0; e < 20; e++) {
                float v = fmaf(tok_next.x, eW[2 * e], tok_next.y * eW[2 * e + 1]);
                act[e * 32 + tid] = fmaxf(v, 0.0f);
            }
            if (t < 510) tok_next = xrow[t + 2];   // prefetch one full step ahead
        }
        __syncthreads();
    }

    // write final h64
    for (int idx = tid; idx < 2048; idx += 256) {
        int bb = idx >> 6, j = idx & 63;
        g_h64[(size_t)(bt * 32 + bb) * 64 + j] = act[(20 + j) * 32 + bb];
    }
}

// ---------------- LSTM2: single step, zero state -> f gate & Whh2 unused ----------------
// shared: Ws[3][64][256] = 49152 floats, hact[64][32] = 2048 floats -> 204800 B
__global__ void __launch_bounds__(256, 1)
lstm2_kernel(const float* __restrict__ Wih2, const float* __restrict__ b2)
{
    extern __shared__ float sm[];
    float* Ws   = sm;            // [type][k][j], type 0:i 1:g 2:o
    float* hact = sm + 49152;    // [k][b]
    const int tid = threadIdx.x;
    const int bt  = blockIdx.x;

    for (int idx = tid; idx < 3 * 64 * 256; idx += 256) {
        int tt = idx >> 14;
        int r  = idx & 16383;
        int k  = r >> 8, j = r & 255;
        int o  = (tt == 0) ? 0 : (tt == 1) ? 512 : 768;  // i, g, o gate offsets
        Ws[idx] = __ldg(&Wih2[(size_t)(o + j) * 64 + k]);
    }
    for (int idx = tid; idx < 2048; idx += 256) {
        int bb = idx >> 6, k = idx & 63;
        hact[k * 32 + bb] = g_h64[(size_t)(bt * 32 + bb) * 64 + k];
    }
    __syncthreads();

    const int w = tid >> 5, l = tid & 31;   // warp -> 4 batches, lane -> j pair
    for (int jc = 0; jc < 4; jc++) {
        int j = jc * 64 + 2 * l;
        ull bI = pk(__ldg(&b2[j]),       __ldg(&b2[j + 1]));
        ull bG = pk(__ldg(&b2[512 + j]), __ldg(&b2[512 + j + 1]));
        ull bO = pk(__ldg(&b2[768 + j]), __ldg(&b2[768 + j + 1]));
        ull aI[4], aG[4], aO[4];
        #pragma unroll
        for (int q = 0; q < 4; q++) { aI[q] = bI; aG[q] = bG; aO[q] = bO; }

        #pragma unroll 4
        for (int k = 0; k < 64; k++) {
            float4 a = *reinterpret_cast<const float4*>(hact + k * 32 + 4 * w);
            ull a0 = pk(a.x, a.x), a1 = pk(a.y, a.y);
            ull a2 = pk(a.z, a.z), a3 = pk(a.w, a.w);
            float2 wi = *reinterpret_cast<const float2*>(Ws + k * 256 + j);
            float2 wg = *reinterpret_cast<const float2*>(Ws + 16384 + k * 256 + j);
            float2 wo = *reinterpret_cast<const float2*>(Ws + 32768 + k * 256 + j);
            ull wpi = pk(wi.x, wi.y), wpg = pk(wg.x, wg.y), wpo = pk(wo.x, wo.y);
            fma2(aI[0], wpi, a0); fma2(aI[1], wpi, a1);
            fma2(aI[2], wpi, a2); fma2(aI[3], wpi, a3);
            fma2(aG[0], wpg, a0); fma2(aG[1], wpg, a1);
            fma2(aG[2], wpg, a2); fma2(aG[3], wpg, a3);
            fma2(aO[0], wpo, a0); fma2(aO[1], wpo, a1);
            fma2(aO[2], wpo, a2); fma2(aO[3], wpo, a3);
        }
        #pragma unroll
        for (int q = 0; q < 4; q++) {
            float2 vi = upk(aI[q]);
            float2 vg = upk(aG[q]);
            float2 vo = upk(aO[q]);
            float c0 = sigf(vi.x) * tanh_(vg.x);
            float h0 = sigf(vo.x) * tanh_(c0);
            float c1 = sigf(vi.y) * tanh_(vg.y);
            float h1 = sigf(vo.y) * tanh_(c1);
            int bb = bt * 32 + 4 * w + q;
            *reinterpret_cast<float2*>(&g_h256[(size_t)bb * 256 + j]) =
                make_float2(h0, h1);
        }
    }
}

// ---------------- output projection: out = h256 @ Wout^T + bout ----------------
__global__ void __launch_bounds__(256)
out_kernel(const float* __restrict__ Wout, const float* __restrict__ bout,
           float* __restrict__ out)
{
    int gw = (blockIdx.x * 256 + threadIdx.x) >> 5;   // one warp per batch elem
    int l  = threadIdx.x & 31;
    if (gw >= 4096) return;
    const float* hrow = g_h256 + (size_t)gw * 256;
    float p0 = 0.0f, p1 = 0.0f;
    #pragma unroll
    for (int m = 0; m < 8; m++) {
        int j = l + 32 * m;
        float h = hrow[j];
        p0 = fmaf(h, __ldg(&Wout[j]), p0);
        p1 = fmaf(h, __ldg(&Wout[256 + j]), p1);
    }
    #pragma unroll
    for (int s = 16; s > 0; s >>= 1) {
        p0 += __shfl_xor_sync(0xffffffffu, p0, s);
        p1 += __shfl_xor_sync(0xffffffffu, p1, s);
    }
    if (l == 0) {
        out[gw * 2]     = p0 + __ldg(&bout[0]);
        out[gw * 2 + 1] = p1 + __ldg(&bout[1]);
    }
}

// ---------------- launch ----------------
extern "C" void kernel_launch(void* const* d_in, const int* in_sizes, int n_in,
                              void* d_out, int out_size)
{
    // map inputs by unique element counts (robust to ordering)
    const float *x = nullptr, *W_embed = nullptr, *Wih1 = nullptr, *Whh1 = nullptr,
                *b1 = nullptr, *Wih2 = nullptr, *b2 = nullptr,
                *Wout = nullptr, *bout = nullptr;
    for (int i = 0; i < n_in; i++) {
        const float* p = (const float*)d_in[i];
        switch (in_sizes[i]) {
            case 4194304: x = p; break;        // (4096, 1024)
            case 40:      W_embed = p; break;  // (20, 2)
            case 5120:    Wih1 = p; break;     // (256, 20)
            case 16384:   Whh1 = p; break;     // (256, 64)
            case 256:     b1 = p; break;       // (256,)
            case 65536:   Wih2 = p; break;     // (1024, 64)
            case 262144:  /* Whh2 unused */ break;
            case 1024:    b2 = p; break;       // (1024,)
            case 512:     Wout = p; break;     // (2, 256)
            case 2:       bout = p; break;     // (2,)
            default: break;
        }
    }
    float* out = (float*)d_out;

    const int SMEM1 = S1_FLOATS * 4;          // 140032 B
    const int SMEM2 = (49152 + 2048) * 4;     // 204800 B
    cudaFuncSetAttribute(lstm1_kernel, cudaFuncAttributeMaxDynamicSharedMemorySize, SMEM1);
    cudaFuncSetAttribute(lstm2_kernel, cudaFuncAttributeMaxDynamicSharedMemorySize, SMEM2);

    lstm1_kernel<<<128, 256, SMEM1>>>(x, W_embed, Wih1, Whh1, b1);
    lstm2_kernel<<<128, 256, SMEM2>>>(Wih2, b2);
    out_kernel<<<512, 256>>>(Wout, bout, out);
    (void)out_size;
}